// round 8
// baseline (speedup 1.0000x reference)
#include <cuda_runtime.h>
#include <cuda_bf16.h>
#include <math.h>

#define HW    12544
#define MTOT  401408
#define NNf   401408.0f
#define NGf   200704.0f

typedef unsigned long long ull;

// ---------------- persistent device scratch (bf16 pair layout for big tensors) ----------------
__device__ __nv_bfloat162 d_h2[64 * MTOT];     // plane op holds channels (2op, 2op+1)
__device__ __nv_bfloat162 d_hact2[64 * MTOT];
__device__ __nv_bfloat162 d_ghn2[64 * MTOT];
__device__ __nv_bfloat162 d_y2[32 * MTOT];     // plane cp holds channels (2cp, 2cp+1)

__device__ float d_gnpart[32 * 12544];
__device__ float d_ypart[512];
__device__ float d_wpart[256 * 6272];
__device__ float d_bpart[32 * 12544];
__device__ float d_gw1part[256 * 8192];
__device__ float d_gw2part[256 * 8192];

__device__ float d_mu[256], d_rstd[256], d_m1[256], d_m2[256];
__device__ float d_gy0[64], d_gyB[64];
__device__ float d_gg[256];
__device__ float d_w1[8192], d_gnw[128], d_gnb[128], d_w2[8192];
__device__ float d_mw1[8192], d_mgw[128], d_mgb[128], d_mw2[8192];
__device__ float d_pooled[2048], d_gate[32];

// ---------------- helpers ----------------
__device__ __forceinline__ float wsum(float v) {
    v += __shfl_down_sync(0xffffffffu, v, 16);
    v += __shfl_down_sync(0xffffffffu, v, 8);
    v += __shfl_down_sync(0xffffffffu, v, 4);
    v += __shfl_down_sync(0xffffffffu, v, 2);
    v += __shfl_down_sync(0xffffffffu, v, 1);
    return v;
}
__device__ __forceinline__ float gelu_f(float v) {
    return 0.5f * v * (1.0f + erff(v * 0.7071067811865475f));
}
__device__ __forceinline__ ull pack2(float lo, float hi) {
    ull r; asm("mov.b64 %0, {%1, %2};" : "=l"(r) : "f"(lo), "f"(hi)); return r;
}
__device__ __forceinline__ void unpack2(ull v, float& lo, float& hi) {
    asm("mov.b64 {%0, %1}, %2;" : "=f"(lo), "=f"(hi) : "l"(v));
}
__device__ __forceinline__ ull fma2(ull a, ull b, ull c) {
    ull d; asm("fma.rn.f32x2 %0, %1, %2, %3;" : "=l"(d) : "l"(a), "l"(b), "l"(c)); return d;
}
__device__ __forceinline__ float hsum2(ull v) {
    float a, b; unpack2(v, a, b); return a + b;
}
__device__ __forceinline__ float2 bf2f(__nv_bfloat162 v) { return __bfloat1622float2(v); }
__device__ __forceinline__ __nv_bfloat162 f2bf(float lo, float hi) { return __floats2bfloat162_rn(lo, hi); }
// pack two fp32 -> bf162 raw bits in a uint register
__device__ __forceinline__ unsigned f2bfu(float lo, float hi) {
    __nv_bfloat162 t = __floats2bfloat162_rn(lo, hi);
    return *(unsigned*)&t;
}
// unpack bf162 bits -> f32x2 ull (lo<<16, hi&mask) via 2 ALU ops
__device__ __forceinline__ ull bfup(unsigned v) {
    unsigned lo = v << 16;
    unsigned hi = v & 0xffff0000u;
    ull r; asm("mov.b64 %0, {%1, %2};" : "=l"(r) : "r"(lo), "r"(hi));
    return r;
}

// ---------------- init ----------------
__global__ void k_init(const float* __restrict__ w1, const float* __restrict__ gnw,
                       const float* __restrict__ gnb, const float* __restrict__ w2) {
    int idx = blockIdx.x * 256 + threadIdx.x;
    if (idx < 8192)       { d_w1[idx] = w1[idx]; d_mw1[idx] = 0.f; }
    else if (idx < 16384) { int i = idx - 8192;  d_w2[i] = w2[i];  d_mw2[i] = 0.f; }
    else if (idx < 16512) { int i = idx - 16384; d_gnw[i] = gnw[i]; d_mgw[i] = 0.f; }
    else if (idx < 16640) { int i = idx - 16512; d_gnb[i] = gnb[i]; d_mgb[i] = 0.f; }
}

// ---------------- pooled = mean_hw(x) ----------------
__global__ void k_pool(const float* __restrict__ x) {
    int c = blockIdx.x, b = blockIdx.y, t = threadIdx.x;
    const float* xp = x + ((size_t)b * 64 + c) * HW;
    float s = 0.f;
    for (int i = t; i < 3136; i += 256) {
        float4 v = *(const float4*)&xp[i * 4];
        s += (v.x + v.y) + (v.z + v.w);
    }
    __shared__ float r[256];
    r[t] = s; __syncthreads();
    for (int st = 128; st; st >>= 1) { if (t < st) r[t] += r[t + st]; __syncthreads(); }
    if (t == 0) d_pooled[b * 64 + c] = r[0] * (1.0f / 12544.0f);
}

// ---------------- gate ----------------
__global__ void k_gate(const float* __restrict__ g1w, const float* __restrict__ g1b,
                       const float* __restrict__ g2w, const float* __restrict__ g2b,
                       const float* __restrict__ rs) {
    int b = threadIdx.x;
    if (b >= 32) return;
    float acc = g2b[0];
    for (int j = 0; j < 16; j++) {
        float a = g1b[j];
        for (int c = 0; c < 64; c++) a = fmaf(d_pooled[b * 64 + c], g1w[j * 64 + c], a);
        acc = fmaf(gelu_f(a), g2w[j], acc);
    }
    d_gate[b] = rs[0] / (1.0f + expf(-acc));
}

// ---------------- conv1: h = W1 x ; GN partial stats. 2 pixels/thread (batch pair) ----------------
__global__ void __launch_bounds__(256) k_conv1(const float* __restrict__ x) {
    __shared__ __align__(16) float w1s[8192];
    int tid = threadIdx.x, by = blockIdx.y, bx = blockIdx.x;
    int b0 = 2 * by, b1 = 2 * by + 1;
    for (int i = tid; i < 8192; i += 256) w1s[i] = d_w1[i];
    __syncthreads();
    int p = bx * 256 + tid;
    int q0 = b0 * HW + p, q1 = b1 * HW + p;
    const float* xb0 = x + (size_t)b0 * 64 * HW + p;
    const float* xb1 = x + (size_t)b1 * 64 * HW + p;
    unsigned xq0[32], xq1[32];            // bf162 channel-pairs per pixel
    #pragma unroll
    for (int c2 = 0; c2 < 32; c2++) {
        xq0[c2] = f2bfu(xb0[(size_t)(2 * c2) * HW], xb0[(size_t)(2 * c2 + 1) * HW]);
        xq1[c2] = f2bfu(xb1[(size_t)(2 * c2) * HW], xb1[(size_t)(2 * c2 + 1) * HW]);
    }
    int lane = tid & 31, wid = tid >> 5;
    int slot0 = (b0 * 49 + bx) * 8 + wid;
    int slot1 = (b1 * 49 + bx) * 8 + wid;
    #pragma unroll 1
    for (int ch = 0; ch < 16; ch++) {
        int o0 = ch * 8;
        ull acc0[8], acc1[8];
        #pragma unroll
        for (int j = 0; j < 8; j++) { acc0[j] = 0ULL; acc1[j] = 0ULL; }
        #pragma unroll
        for (int c4 = 0; c4 < 16; c4++) {
            ull xA0 = bfup(xq0[2 * c4]),     xB0 = bfup(xq0[2 * c4 + 1]);
            ull xA1 = bfup(xq1[2 * c4]),     xB1 = bfup(xq1[2 * c4 + 1]);
            #pragma unroll
            for (int j = 0; j < 8; j++) {
                ulonglong2 wp = *(const ulonglong2*)&w1s[(o0 + j) * 64 + c4 * 4];
                acc0[j] = fma2(wp.x, xA0, acc0[j]);
                acc0[j] = fma2(wp.y, xB0, acc0[j]);
                acc1[j] = fma2(wp.x, xA1, acc1[j]);
                acc1[j] = fma2(wp.y, xB1, acc1[j]);
            }
        }
        float hv0[8], hv1[8];
        float cs0 = 0.f, cs20 = 0.f, cs1 = 0.f, cs21 = 0.f;
        #pragma unroll
        for (int j = 0; j < 8; j++) {
            hv0[j] = hsum2(acc0[j]);
            hv1[j] = hsum2(acc1[j]);
            cs0 += hv0[j]; cs20 = fmaf(hv0[j], hv0[j], cs20);
            cs1 += hv1[j]; cs21 = fmaf(hv1[j], hv1[j], cs21);
        }
        #pragma unroll
        for (int jj = 0; jj < 4; jj++) {
            d_h2[(size_t)(ch * 4 + jj) * MTOT + q0] = f2bf(hv0[2 * jj], hv0[2 * jj + 1]);
            d_h2[(size_t)(ch * 4 + jj) * MTOT + q1] = f2bf(hv1[2 * jj], hv1[2 * jj + 1]);
        }
        float s0 = wsum(cs0), s20 = wsum(cs20);
        float s1 = wsum(cs1), s21 = wsum(cs21);
        if (lane == 0) {
            d_gnpart[ch * 12544 + slot0] = s0;
            d_gnpart[(16 + ch) * 12544 + slot0] = s20;
            d_gnpart[ch * 12544 + slot1] = s1;
            d_gnpart[(16 + ch) * 12544 + slot1] = s21;
        }
    }
}

// ---------------- reduce GN stats -> mu, rstd per (b,g) ----------------
__global__ void k_gnred() {
    int t = blockIdx.x;
    int b = t >> 3, g = t & 7;
    int tid = threadIdx.x;
    float s = 0.f, s2 = 0.f;
    for (int i = tid; i < 392; i += 128) {
        int sl = b * 392 + i;
        s  += d_gnpart[(2 * g) * 12544 + sl] + d_gnpart[(2 * g + 1) * 12544 + sl];
        s2 += d_gnpart[(16 + 2 * g) * 12544 + sl] + d_gnpart[(16 + 2 * g + 1) * 12544 + sl];
    }
    __shared__ float r1[128], r2[128];
    r1[tid] = s; r2[tid] = s2; __syncthreads();
    for (int st = 64; st; st >>= 1) {
        if (tid < st) { r1[tid] += r1[tid + st]; r2[tid] += r2[tid + st]; }
        __syncthreads();
    }
    if (tid == 0) {
        float m = r1[0] * (1.0f / NGf);
        float var = r2[0] * (1.0f / NGf) - m * m;
        d_mu[t] = m;
        d_rstd[t] = rsqrtf(var + 1e-5f);
    }
}

// ---------------- fwd2: hact=gelu(GN(h)); y = W2 hact + x ----------------
__global__ void __launch_bounds__(256) k_fwd2(const float* __restrict__ x) {
    __shared__ __align__(16) float w2t[8192];   // transposed [o][c]
    __shared__ float sgw[128], sgb[128], smu[8], srs[8];
    int tid = threadIdx.x, b = blockIdx.y, bx = blockIdx.x;
    for (int i = tid; i < 8192; i += 256) { int c = i >> 7, o = i & 127; w2t[o * 64 + c] = d_w2[i]; }
    if (tid < 128) { sgw[tid] = d_gnw[tid]; sgb[tid] = d_gnb[tid]; }
    if (tid < 8) { smu[tid] = d_mu[b * 8 + tid]; srs[tid] = d_rstd[b * 8 + tid]; }
    __syncthreads();
    int p = bx * 256 + tid;
    int q = b * HW + p;
    ull mp[32];
    #pragma unroll
    for (int i = 0; i < 32; i++) mp[i] = 0ULL;
    #pragma unroll 1
    for (int o2 = 0; o2 < 64; o2++) {
        int o0 = 2 * o2, g = o0 >> 4;
        float2 hf = bf2f(d_h2[(size_t)o2 * MTOT + q]);
        float haff0 = (hf.x - smu[g]) * srs[g] * sgw[o0] + sgb[o0];
        float haff1 = (hf.y - smu[g]) * srs[g] * sgw[o0 + 1] + sgb[o0 + 1];
        float ha0 = gelu_f(haff0), ha1 = gelu_f(haff1);
        ull hap0 = pack2(ha0, ha0), hap1 = pack2(ha1, ha1);
        #pragma unroll
        for (int c4 = 0; c4 < 16; c4++) {
            ulonglong2 w0 = *(const ulonglong2*)&w2t[o0 * 64 + c4 * 4];
            ulonglong2 w1 = *(const ulonglong2*)&w2t[(o0 + 1) * 64 + c4 * 4];
            mp[c4 * 2]     = fma2(w0.x, hap0, mp[c4 * 2]);
            mp[c4 * 2 + 1] = fma2(w0.y, hap0, mp[c4 * 2 + 1]);
            mp[c4 * 2]     = fma2(w1.x, hap1, mp[c4 * 2]);
            mp[c4 * 2 + 1] = fma2(w1.y, hap1, mp[c4 * 2 + 1]);
        }
    }
    const float* xb = x + (size_t)b * 64 * HW + p;
    #pragma unroll
    for (int i = 0; i < 32; i++) {
        float lo, hi; unpack2(mp[i], lo, hi);
        lo += xb[(size_t)(2 * i) * HW];
        hi += xb[(size_t)(2 * i + 1) * HW];
        d_y2[(size_t)i * MTOT + q] = f2bf(lo, hi);
    }
}

// ---------------- y stats partials (per pair-plane) ----------------
__global__ void k_ystat() {
    int i = blockIdx.x, cp = blockIdx.y, tid = threadIdx.x;
    const __nv_bfloat162* yp = d_y2 + (size_t)cp * MTOT + (size_t)i * 100352;
    float slo = 0.f, s2lo = 0.f, shi = 0.f, s2hi = 0.f;
    for (int k = tid; k < 25088; k += 256) {
        uint4 raw = *(const uint4*)&yp[k * 4];
        const unsigned v4[4] = {raw.x, raw.y, raw.z, raw.w};
        #pragma unroll
        for (int j = 0; j < 4; j++) {
            float2 f = bf2f(*(const __nv_bfloat162*)&v4[j]);
            slo += f.x; s2lo = fmaf(f.x, f.x, s2lo);
            shi += f.y; s2hi = fmaf(f.y, f.y, s2hi);
        }
    }
    __shared__ float r1[256], r2[256], r3[256], r4[256];
    r1[tid] = slo; r2[tid] = s2lo; r3[tid] = shi; r4[tid] = s2hi;
    __syncthreads();
    for (int st = 128; st; st >>= 1) {
        if (tid < st) {
            r1[tid] += r1[tid + st]; r2[tid] += r2[tid + st];
            r3[tid] += r3[tid + st]; r4[tid] += r4[tid + st];
        }
        __syncthreads();
    }
    if (tid == 0) {
        int c0 = 2 * cp;
        d_ypart[c0 * 4 + i] = r1[0];       d_ypart[256 + c0 * 4 + i] = r2[0];
        d_ypart[(c0 + 1) * 4 + i] = r3[0]; d_ypart[256 + (c0 + 1) * 4 + i] = r4[0];
    }
}

// ---------------- gy0, gyB ----------------
__global__ void k_gy(const float* __restrict__ rm, const float* __restrict__ rv) {
    int c = threadIdx.x;
    if (c >= 64) return;
    float s = 0.f, s2 = 0.f;
    for (int i = 0; i < 4; i++) { s += d_ypart[c * 4 + i]; s2 += d_ypart[256 + c * 4 + i]; }
    float cm = s / NNf;
    float cv = (s2 - NNf * cm * cm) / (NNf - 1.0f);
    float rvp = rv[c] + 1e-8f;
    float gyB = 4.0f * (cv / rvp - 1.0f) / (64.0f * rvp * (NNf - 1.0f));
    float gy0 = 2.0f * (cm - rm[c]) / (64.0f * NNf) - gyB * cm;
    d_gy0[c] = gy0; d_gyB[c] = gyB;
}

// ---------------- bwd1: 2 pixels/thread (batch pair) ----------------
__global__ void __launch_bounds__(256) k_bwd1() {
    __shared__ __align__(16) float w2t[8192];   // transposed [o][c]
    __shared__ float sgw[128], sgb[128], smu[16], srs[16], sg0[64], sgB[64];
    int tid = threadIdx.x, by = blockIdx.y, bx = blockIdx.x;
    int b0 = 2 * by, b1 = 2 * by + 1;
    for (int i = tid; i < 8192; i += 256) { int c = i >> 7, o = i & 127; w2t[o * 64 + c] = d_w2[i]; }
    if (tid < 128) { sgw[tid] = d_gnw[tid]; sgb[tid] = d_gnb[tid]; }
    if (tid < 64) { sg0[tid] = d_gy0[tid]; sgB[tid] = d_gyB[tid]; }
    if (tid < 16) { smu[tid] = d_mu[b0 * 8 + tid]; srs[tid] = d_rstd[b0 * 8 + tid]; }
    __syncthreads();
    int p = bx * 256 + tid;
    int q0 = b0 * HW + p, q1 = b1 * HW + p;
    int lane = tid & 31, wid = tid >> 5;
    int slotw = (by * 49 + bx) * 8 + wid;         // 6272-slot space for global sums
    int slot0 = (b0 * 49 + bx) * 8 + wid;         // per-batch slots for GN stats
    int slot1 = (b1 * 49 + bx) * 8 + wid;
    unsigned gyq0[32], gyq1[32];                  // bf162 channel-pairs of g_y per pixel
    #pragma unroll
    for (int c2 = 0; c2 < 32; c2++) {
        float2 y0 = bf2f(d_y2[(size_t)c2 * MTOT + q0]);
        float2 y1 = bf2f(d_y2[(size_t)c2 * MTOT + q1]);
        gyq0[c2] = f2bfu(sg0[2 * c2] + sgB[2 * c2] * y0.x, sg0[2 * c2 + 1] + sgB[2 * c2 + 1] * y0.y);
        gyq1[c2] = f2bfu(sg0[2 * c2] + sgB[2 * c2] * y1.x, sg0[2 * c2 + 1] + sgB[2 * c2 + 1] * y1.y);
    }
    #pragma unroll 1
    for (int ch = 0; ch < 16; ch++) {
        int o0 = ch * 8, g = ch >> 1;
        ull acc0[8], acc1[8];
        #pragma unroll
        for (int j = 0; j < 8; j++) { acc0[j] = 0ULL; acc1[j] = 0ULL; }
        #pragma unroll
        for (int c4 = 0; c4 < 16; c4++) {
            ull gA0 = bfup(gyq0[2 * c4]), gB0 = bfup(gyq0[2 * c4 + 1]);
            ull gA1 = bfup(gyq1[2 * c4]), gB1 = bfup(gyq1[2 * c4 + 1]);
            #pragma unroll
            for (int j = 0; j < 8; j++) {
                ulonglong2 wp = *(const ulonglong2*)&w2t[(o0 + j) * 64 + c4 * 4];
                acc0[j] = fma2(wp.x, gA0, acc0[j]);
                acc0[j] = fma2(wp.y, gB0, acc0[j]);
                acc1[j] = fma2(wp.x, gA1, acc1[j]);
                acc1[j] = fma2(wp.y, gB1, acc1[j]);
            }
        }
        float m10 = 0.f, m20 = 0.f, m11 = 0.f, m21 = 0.f;
        float pgw[8], pgb[8];
        #pragma unroll
        for (int jj = 0; jj < 4; jj++) {
            float2 hf0 = bf2f(d_h2[(size_t)(ch * 4 + jj) * MTOT + q0]);
            float2 hf1 = bf2f(d_h2[(size_t)(ch * 4 + jj) * MTOT + q1]);
            float hav0[2], ghv0[2], hav1[2], ghv1[2];
            float hvs0[2] = {hf0.x, hf0.y};
            float hvs1[2] = {hf1.x, hf1.y};
            #pragma unroll
            for (int e = 0; e < 2; e++) {
                int j = 2 * jj + e, o = o0 + j;
                // pixel 0
                {
                    float ghact = hsum2(acc0[j]);
                    float hn = (hvs0[e] - smu[g]) * srs[g];
                    float haff = hn * sgw[o] + sgb[o];
                    float cdf = 0.5f * (1.0f + erff(haff * 0.7071067811865475f));
                    float pdf = 0.3989422804014327f * expf(-0.5f * haff * haff);
                    hav0[e] = haff * cdf;
                    float dg = fmaf(haff, pdf, cdf);
                    float ghaff = ghact * dg;
                    float ghn = ghaff * sgw[o];
                    ghv0[e] = ghn;
                    pgw[j] = ghaff * hn; pgb[j] = ghaff;
                    m10 += ghn; m20 = fmaf(ghn, hn, m20);
                }
                // pixel 1
                {
                    float ghact = hsum2(acc1[j]);
                    float hn = (hvs1[e] - smu[8 + g]) * srs[8 + g];
                    float haff = hn * sgw[o] + sgb[o];
                    float cdf = 0.5f * (1.0f + erff(haff * 0.7071067811865475f));
                    float pdf = 0.3989422804014327f * expf(-0.5f * haff * haff);
                    hav1[e] = haff * cdf;
                    float dg = fmaf(haff, pdf, cdf);
                    float ghaff = ghact * dg;
                    float ghn = ghaff * sgw[o];
                    ghv1[e] = ghn;
                    pgw[j] += ghaff * hn; pgb[j] += ghaff;
                    m11 += ghn; m21 = fmaf(ghn, hn, m21);
                }
            }
            d_hact2[(size_t)(ch * 4 + jj) * MTOT + q0] = f2bf(hav0[0], hav0[1]);
            d_hact2[(size_t)(ch * 4 + jj) * MTOT + q1] = f2bf(hav1[0], hav1[1]);
            d_ghn2[(size_t)(ch * 4 + jj) * MTOT + q0]  = f2bf(ghv0[0], ghv0[1]);
            d_ghn2[(size_t)(ch * 4 + jj) * MTOT + q1]  = f2bf(ghv1[0], ghv1[1]);
        }
        #pragma unroll
        for (int j = 0; j < 8; j++) {
            float s = wsum(pgw[j]), s2 = wsum(pgb[j]);
            if (lane == 0) {
                d_wpart[(o0 + j) * 6272 + slotw] = s;
                d_wpart[(128 + o0 + j) * 6272 + slotw] = s2;
            }
        }
        float sm10 = wsum(m10), sm20 = wsum(m20);
        float sm11 = wsum(m11), sm21 = wsum(m21);
        if (lane == 0) {
            d_bpart[ch * 12544 + slot0] = sm10;
            d_bpart[(16 + ch) * 12544 + slot0] = sm20;
            d_bpart[ch * 12544 + slot1] = sm11;
            d_bpart[(16 + ch) * 12544 + slot1] = sm21;
        }
    }
}

// ---------------- reduce m1,m2 per (b,g) and gnw/gnb grads ----------------
__global__ void k_mred() {
    int bid = blockIdx.x, tid = threadIdx.x;
    __shared__ float r1[256], r2[256];
    if (bid < 256) {
        int b = bid >> 3, g = bid & 7;
        float s1 = 0.f, s2 = 0.f;
        for (int i = tid; i < 392; i += 256) {
            int sl = b * 392 + i;
            s1 += d_bpart[(2 * g) * 12544 + sl] + d_bpart[(2 * g + 1) * 12544 + sl];
            s2 += d_bpart[(16 + 2 * g) * 12544 + sl] + d_bpart[(16 + 2 * g + 1) * 12544 + sl];
        }
        r1[tid] = s1; r2[tid] = s2; __syncthreads();
        for (int st = 128; st; st >>= 1) {
            if (tid < st) { r1[tid] += r1[tid + st]; r2[tid] += r2[tid + st]; }
            __syncthreads();
        }
        if (tid == 0) { d_m1[bid] = r1[0] * (1.0f / NGf); d_m2[bid] = r2[0] * (1.0f / NGf); }
    } else {
        int row = bid - 256;
        float s = 0.f;
        for (int i = tid; i < 6272; i += 256) s += d_wpart[row * 6272 + i];
        r1[tid] = s; __syncthreads();
        for (int st = 128; st; st >>= 1) {
            if (tid < st) r1[tid] += r1[tid + st];
            __syncthreads();
        }
        if (tid == 0) d_gg[row] = r1[0];
    }
}

// ---------------- gw2 = sum g_y * hact^T (pad 36, 128-bit kk-paired LDS) ----------------
__global__ void __launch_bounds__(256) k_gw2red() {
    __shared__ __align__(16) float gys[64 * 36];
    __shared__ __align__(16) float hacts[128 * 36];
    __shared__ float sg0[64], sgB[64];
    int tid = threadIdx.x, bidx = blockIdx.x;
    int tx = tid & 15, ty = tid >> 4;
    if (tid < 64) { sg0[tid] = d_gy0[tid]; sgB[tid] = d_gyB[tid]; }
    size_t q0 = (size_t)bidx * 1568;
    ull accp[4][8];
    #pragma unroll
    for (int j = 0; j < 4; j++)
        #pragma unroll
        for (int i = 0; i < 8; i++) accp[j][i] = 0ULL;
    int k = tid & 31, r0 = tid >> 5;
    for (int chunk = 0; chunk < 49; chunk++) {
        size_t qc = q0 + chunk * 32;
        __syncthreads();
        #pragma unroll
        for (int rep = 0; rep < 4; rep++) {
            int cp = r0 + rep * 8;
            float2 v = bf2f(d_y2[(size_t)cp * MTOT + qc + k]);
            gys[(2 * cp) * 36 + k]     = sg0[2 * cp]     + sgB[2 * cp]     * v.x;
            gys[(2 * cp + 1) * 36 + k] = sg0[2 * cp + 1] + sgB[2 * cp + 1] * v.y;
        }
        #pragma unroll
        for (int rep = 0; rep < 8; rep++) {
            int op = r0 + rep * 8;
            float2 v = bf2f(d_hact2[(size_t)op * MTOT + qc + k]);
            hacts[(2 * op) * 36 + k]     = v.x;
            hacts[(2 * op + 1) * 36 + k] = v.y;
        }
        __syncthreads();
        #pragma unroll 2
        for (int kk4 = 0; kk4 < 8; kk4++) {
            ulonglong2 gvp[4], hvp[8];
            #pragma unroll
            for (int j = 0; j < 4; j++) gvp[j] = *(const ulonglong2*)&gys[(ty * 4 + j) * 36 + kk4 * 4];
            #pragma unroll
            for (int i = 0; i < 8; i++) hvp[i] = *(const ulonglong2*)&hacts[(tx + 16 * i) * 36 + kk4 * 4];
            #pragma unroll
            for (int j = 0; j < 4; j++)
                #pragma unroll
                for (int i = 0; i < 8; i++) {
                    accp[j][i] = fma2(gvp[j].x, hvp[i].x, accp[j][i]);
                    accp[j][i] = fma2(gvp[j].y, hvp[i].y, accp[j][i]);
                }
        }
    }
    #pragma unroll
    for (int j = 0; j < 4; j++)
        #pragma unroll
        for (int i = 0; i < 8; i++)
            d_gw2part[(size_t)bidx * 8192 + (ty * 4 + j) * 128 + (tx + 16 * i)] = hsum2(accp[j][i]);
}

// ---------------- gw1 = sum g_h * x^T (GN backward fused; pad 36, 128-bit LDS) ----------------
__global__ void __launch_bounds__(256) k_gw1red(const float* __restrict__ x) {
    __shared__ __align__(16) float ghs[128 * 36];
    __shared__ __align__(16) float xs[64 * 36];
    __shared__ float smu[8], srs[8], sm1[8], sm2[8];
    int tid = threadIdx.x, bidx = blockIdx.x;
    int tx = tid & 15, ty = tid >> 4;
    int b = bidx >> 3;
    if (tid < 8) {
        smu[tid] = d_mu[b * 8 + tid]; srs[tid] = d_rstd[b * 8 + tid];
        sm1[tid] = d_m1[b * 8 + tid]; sm2[tid] = d_m2[b * 8 + tid];
    }
    size_t q0 = (size_t)bidx * 1568;
    int p0 = (int)(q0 - (size_t)b * HW);
    ull accp[8][4];
    #pragma unroll
    for (int i = 0; i < 8; i++)
        #pragma unroll
        for (int j = 0; j < 4; j++) accp[i][j] = 0ULL;
    int k = tid & 31, r0 = tid >> 5;
    const float* xb = x + (size_t)b * 64 * HW;
    for (int chunk = 0; chunk < 49; chunk++) {
        size_t qc = q0 + chunk * 32;
        int pc = p0 + chunk * 32;
        __syncthreads();
        #pragma unroll
        for (int rep = 0; rep < 8; rep++) {
            int op = r0 + rep * 8, g = (2 * op) >> 4;
            float2 hv = bf2f(d_h2[(size_t)op * MTOT + qc + k]);
            float2 gv = bf2f(d_ghn2[(size_t)op * MTOT + qc + k]);
            float hn0 = (hv.x - smu[g]) * srs[g];
            float hn1 = (hv.y - smu[g]) * srs[g];
            ghs[(2 * op) * 36 + k]     = srs[g] * (gv.x - sm1[g] - hn0 * sm2[g]);
            ghs[(2 * op + 1) * 36 + k] = srs[g] * (gv.y - sm1[g] - hn1 * sm2[g]);
        }
        #pragma unroll
        for (int rep = 0; rep < 8; rep++) {
            int c = r0 + rep * 8;
            xs[c * 36 + k] = xb[(size_t)c * HW + pc + k];
        }
        __syncthreads();
        #pragma unroll 2
        for (int kk4 = 0; kk4 < 8; kk4++) {
            ulonglong2 hvp[8], xvp[4];
            #pragma unroll
            for (int i = 0; i < 8; i++) hvp[i] = *(const ulonglong2*)&ghs[(tx + 16 * i) * 36 + kk4 * 4];
            #pragma unroll
            for (int j = 0; j < 4; j++) xvp[j] = *(const ulonglong2*)&xs[(ty * 4 + j) * 36 + kk4 * 4];
            #pragma unroll
            for (int i = 0; i < 8; i++)
                #pragma unroll
                for (int j = 0; j < 4; j++) {
                    accp[i][j] = fma2(hvp[i].x, xvp[j].x, accp[i][j]);
                    accp[i][j] = fma2(hvp[i].y, xvp[j].y, accp[i][j]);
                }
        }
    }
    #pragma unroll
    for (int i = 0; i < 8; i++)
        #pragma unroll
        for (int j = 0; j < 4; j++)
            d_gw1part[(size_t)bidx * 8192 + (tx + 16 * i) * 64 + (ty * 4 + j)] = hsum2(accp[i][j]);
}

// ---------------- momentum + param update ----------------
__global__ void k_update() {
    int idx = blockIdx.x * 256 + threadIdx.x;
    if (idx < 8192) {
        float g = 0.f;
        for (int blk = 0; blk < 256; blk++) g += d_gw2part[(size_t)blk * 8192 + idx];
        float m = fmaf(0.9f, d_mw2[idx], g);
        d_mw2[idx] = m;
        d_w2[idx] -= 0.01f * m;
    } else if (idx < 16384) {
        int j = idx - 8192;
        float g = 0.f;
        for (int blk = 0; blk < 256; blk++) g += d_gw1part[(size_t)blk * 8192 + j];
        float m = fmaf(0.9f, d_mw1[j], g);
        d_mw1[j] = m;
        d_w1[j] -= 0.01f * m;
    } else if (idx < 16512) {
        int o = idx - 16384;
        float m = fmaf(0.9f, d_mgw[o], d_gg[o]);
        d_mgw[o] = m;
        d_gnw[o] -= 0.01f * m;
    } else if (idx < 16640) {
        int o = idx - 16512;
        float m = fmaf(0.9f, d_mgb[o], d_gg[128 + o]);
        d_mgb[o] = m;
        d_gnb[o] -= 0.01f * m;
    }
}

// ---------------- final forward: out = x + gate*mod ----------------
__global__ void __launch_bounds__(256) k_fwdout(const float* __restrict__ x, float* __restrict__ out) {
    __shared__ __align__(16) float w2t[8192];
    __shared__ float sgw[128], sgb[128], smu[8], srs[8];
    int tid = threadIdx.x, b = blockIdx.y, bx = blockIdx.x;
    for (int i = tid; i < 8192; i += 256) { int c = i >> 7, o = i & 127; w2t[o * 64 + c] = d_w2[i]; }
    if (tid < 128) { sgw[tid] = d_gnw[tid]; sgb[tid] = d_gnb[tid]; }
    if (tid < 8) { smu[tid] = d_mu[b * 8 + tid]; srs[tid] = d_rstd[b * 8 + tid]; }
    __syncthreads();
    int p = bx * 256 + tid;
    int q = b * HW + p;
    ull mp[32];
    #pragma unroll
    for (int i = 0; i < 32; i++) mp[i] = 0ULL;
    #pragma unroll 1
    for (int o2 = 0; o2 < 64; o2++) {
        int o0 = 2 * o2, g = o0 >> 4;
        float2 hf = bf2f(d_h2[(size_t)o2 * MTOT + q]);
        float haff0 = (hf.x - smu[g]) * srs[g] * sgw[o0] + sgb[o0];
        float haff1 = (hf.y - smu[g]) * srs[g] * sgw[o0 + 1] + sgb[o0 + 1];
        float ha0 = gelu_f(haff0), ha1 = gelu_f(haff1);
        ull hap0 = pack2(ha0, ha0), hap1 = pack2(ha1, ha1);
        #pragma unroll
        for (int c4 = 0; c4 < 16; c4++) {
            ulonglong2 w0 = *(const ulonglong2*)&w2t[o0 * 64 + c4 * 4];
            ulonglong2 w1 = *(const ulonglong2*)&w2t[(o0 + 1) * 64 + c4 * 4];
            mp[c4 * 2]     = fma2(w0.x, hap0, mp[c4 * 2]);
            mp[c4 * 2 + 1] = fma2(w0.y, hap0, mp[c4 * 2 + 1]);
            mp[c4 * 2]     = fma2(w1.x, hap1, mp[c4 * 2]);
            mp[c4 * 2 + 1] = fma2(w1.y, hap1, mp[c4 * 2 + 1]);
        }
    }
    const float* xb = x + (size_t)b * 64 * HW + p;
    float* ob = out + (size_t)b * 64 * HW + p;
    float gt = d_gate[b];
    #pragma unroll
    for (int i = 0; i < 32; i++) {
        float lo, hi; unpack2(mp[i], lo, hi);
        ob[(size_t)(2 * i) * HW]     = fmaf(gt, lo, xb[(size_t)(2 * i) * HW]);
        ob[(size_t)(2 * i + 1) * HW] = fmaf(gt, hi, xb[(size_t)(2 * i + 1) * HW]);
    }
}

extern "C" void kernel_launch(void* const* d_in, const int* in_sizes, int n_in,
                              void* d_out, int out_size) {
    const float* x   = (const float*)d_in[0];
    const float* w1  = (const float*)d_in[1];
    const float* gnw = (const float*)d_in[2];
    const float* gnb = (const float*)d_in[3];
    const float* w2  = (const float*)d_in[4];
    const float* g1w = (const float*)d_in[5];
    const float* g1b = (const float*)d_in[6];
    const float* g2w = (const float*)d_in[7];
    const float* g2b = (const float*)d_in[8];
    const float* rm  = (const float*)d_in[9];
    const float* rv  = (const float*)d_in[10];
    const float* rs  = (const float*)d_in[11];
    float* out = (float*)d_out;

    dim3 g49x32(49, 32);
    dim3 g49x16(49, 16);
    k_init<<<65, 256>>>(w1, gnw, gnb, w2);
    k_pool<<<dim3(64, 32), 256>>>(x);
    k_gate<<<1, 32>>>(g1w, g1b, g2w, g2b, rs);

    for (int step = 0; step < 2; step++) {
        k_conv1<<<g49x16, 256>>>(x);
        k_gnred<<<256, 128>>>();
        k_fwd2<<<g49x32, 256>>>(x);
        k_ystat<<<dim3(4, 32), 256>>>();
        k_gy<<<1, 64>>>(rm, rv);
        k_bwd1<<<g49x16, 256>>>();
        k_mred<<<512, 256>>>();
        k_gw2red<<<256, 256>>>();
        k_gw1red<<<256, 256>>>(x);
        k_update<<<65, 256>>>();
    }
    k_conv1<<<g49x16, 256>>>(x);
    k_gnred<<<256, 128>>>();
    k_fwdout<<<g49x32, 256>>>(x, out);
}